// round 9
// baseline (speedup 1.0000x reference)
#include <cuda_runtime.h>
#include <cuda_fp16.h>
#include <cstdint>

#define B_   8192
#define N_   40
#define F_   256
#define NF   10240
#define TOT  83886080

// ---------------- device scratch (no allocation allowed) --------------------
__device__ __align__(256) __half g_Ahi[TOT];
__device__ __align__(256) __half g_Alo[TOT];
__device__ __align__(256) __half g_Yh[TOT];        // fp16 Y
__device__ __align__(256) __half g_Whi[F_ * F_];   // K-major [fout][fin]
__device__ float g_sp[40 * 64 * 2 * 256];          // [n][bg][stat][col]
__device__ float g_sp2[40 * 8 * 2 * 256];          // [n][y][stat][col]
__device__ float g_scale[NF];
__device__ float g_shift[NF];
__device__ int   g_cnt[64];                        // per-bg k1 completion

// ---------------- helpers ---------------------------------------------------
__device__ __forceinline__ uint32_t smem_u32(const void* p) {
    uint32_t a;
    asm("{ .reg .u64 t; cvta.to.shared.u64 t, %1; cvt.u32.u64 %0, t; }" : "=r"(a) : "l"(p));
    return a;
}
__device__ __forceinline__ void cp16(uint32_t dst, const void* src) {
    asm volatile("cp.async.cg.shared.global [%0], [%1], 16;" :: "r"(dst), "l"(src));
}
#define CP_COMMIT() asm volatile("cp.async.commit_group;" ::: "memory")
#define CP_WAIT(n)  asm volatile("cp.async.wait_group %0;" :: "n"(n) : "memory")

#define LDSM4(r, addr)                                                          \
    asm volatile("ldmatrix.sync.aligned.m8n8.x4.shared.b16 {%0,%1,%2,%3}, [%4];"\
        : "=r"((r)[0]), "=r"((r)[1]), "=r"((r)[2]), "=r"((r)[3]) : "r"(addr))

#define MMA(c, a, b)                                                            \
    asm volatile("mma.sync.aligned.m16n8k16.row.col.f32.f16.f16.f32 "           \
        "{%0,%1,%2,%3}, {%4,%5,%6,%7}, {%8,%9}, {%0,%1,%2,%3};"                 \
        : "+f"((c)[0]), "+f"((c)[1]), "+f"((c)[2]), "+f"((c)[3])                \
        : "r"((a)[0]), "r"((a)[1]), "r"((a)[2]), "r"((a)[3]),                   \
          "r"((b)[0]), "r"((b)[1]))

// ---------------------------------------------------------------------------
// K0: W prep + counter reset (runs before k1 and k2 every replay).
// ---------------------------------------------------------------------------
__global__ void k0_wprep(const float* __restrict__ W) {
    int k = blockIdx.x, n = threadIdx.x;
    if (blockIdx.x == 0 && threadIdx.x < 64) g_cnt[threadIdx.x] = 0;
    g_Whi[n * 256 + k] = __float2half_rn(W[k * 256 + n]);
}

// ---------------------------------------------------------------------------
// K1: blockdiag bmm -> fp16 hi/lo; bumps per-bg counter.  grid (4, 8192).
// ---------------------------------------------------------------------------
__global__ void k1_blockdiag(const float* __restrict__ input,
                             const float* __restrict__ adj) {
    const int b = blockIdx.y;
    const int s = blockIdx.x * 10;
    const int f = threadIdx.x;

    __shared__ float sadj[10][10];
    if (f < 100)
        sadj[f / 10][f % 10] = adj[((size_t)b * 40 + s + f / 10) * 40 + s + f % 10];
    __syncthreads();

    const float* ip = input + ((size_t)b * 40 + s) * 256 + f;
    float x[10];
#pragma unroll
    for (int c = 0; c < 10; ++c) x[c] = ip[c * 256];

    const size_t ob = ((size_t)b * 40 + s) * 256 + f;
#pragma unroll
    for (int r = 0; r < 10; ++r) {
        float acc = 0.f;
#pragma unroll
        for (int c = 0; c < 10; ++c) acc = fmaf(sadj[r][c], x[c], acc);
        __half h = __float2half_rn(acc);
        g_Ahi[ob + (size_t)r * 256] = h;
        g_Alo[ob + (size_t)r * 256] = __float2half_rn(acc - __half2float(h));
    }
    __threadfence();                              // release A stores
    __syncthreads();
    if (f == 0) atomicAdd(&g_cnt[b >> 7], 1);     // 512 arrivals per bg
}

// ---------------------------------------------------------------------------
// K2: fp16-split 2-pass HMMA GEMM + fused stats, fp16 Y out. Single launch,
// per-CTA spin-gated on k1 progress (deadlock-safe: 192KB smem leaves room
// for k1 CTAs on every SM; k2 runs on a low-priority stream).
// smem: [B resident 131072][A double-buffer 2 x 32768] = 196608.
// ---------------------------------------------------------------------------
#define SMEM_K2 196608

__global__ __launch_bounds__(256, 1) void k2_gemm_stats() {
    extern __shared__ char smem[];
    const uint32_t sb = smem_u32(smem);
    const int tid = threadIdx.x, lane = tid & 31, wid = tid >> 5;
    const int wr = wid >> 1, wc = wid & 1;
    const int n = blockIdx.x;
    const int bg = blockIdx.y;

    const char* aH = (const char*)g_Ahi + ((size_t)bg * 128 * 40 + n) * 512;
    const char* aL = (const char*)g_Alo + ((size_t)bg * 128 * 40 + n) * 512;

    // ---- resident B: [kcc 4][256 rows of 128B, swizzled] (group 0) ----
    {
        const char* bB = (const char*)g_Whi;
#pragma unroll
        for (int it = 0; it < 32; ++it) {
            int u = it * 256 + tid;                // 16B units
            int kcc = u >> 11, r = (u >> 3) & 255, o = u & 7;
            size_t gb = (size_t)r * 512 + (size_t)kcc * 128 + o * 16;
            uint32_t so = (uint32_t)kcc * 32768 + r * 128 + ((o ^ (r & 7)) << 4);
            cp16(sb + so, bB + gb);
        }
        CP_COMMIT();
    }

    // ---- wait for k1 to finish this bg ----
    if (tid == 0) {
        while (*(volatile int*)&g_cnt[bg] < 512) __nanosleep(200);
    }
    __syncthreads();
    __threadfence();                               // acquire A stores

    auto loadA = [&](int kcc, int buf) {
        const uint32_t s0 = sb + 131072 + (uint32_t)buf * 32768;
#pragma unroll
        for (int it = 0; it < 4; ++it) {
            int u = it * 256 + tid;
            int r = u >> 3, o = u & 7;
            size_t ga = (size_t)r * 20480 + (size_t)kcc * 128 + o * 16;
            uint32_t so = r * 128 + ((o ^ (r & 7)) << 4);
            cp16(s0 + so,         aH + ga);
            cp16(s0 + 16384 + so, aL + ga);
        }
    };
    loadA(0, 0);
    CP_COMMIT();

    float acc[2][16][4];
#pragma unroll
    for (int mt = 0; mt < 2; ++mt)
#pragma unroll
        for (int nt = 0; nt < 16; ++nt)
#pragma unroll
            for (int q = 0; q < 4; ++q) acc[mt][nt][q] = 0.f;

    const int aRow0 = wr * 32 + (lane & 15);
    const int aKU = lane >> 4;
    const int aSw = lane & 7;
    const int bN0 = wc * 128 + (lane & 7) + ((lane >> 4) & 1) * 8;
    const int bKU = (lane >> 3) & 1;

    int buf = 0;
#pragma unroll
    for (int kcc = 0; kcc < 4; ++kcc) {
        if (kcc < 3) {
            loadA(kcc + 1, buf ^ 1);
            CP_COMMIT();
            CP_WAIT(1);
        } else {
            CP_WAIT(0);
        }
        __syncthreads();

        const uint32_t as = sb + 131072 + (uint32_t)buf * 32768;
        const uint32_t bs = sb + (uint32_t)kcc * 32768;
#pragma unroll
        for (int kk = 0; kk < 4; ++kk) {
            uint32_t ahi[2][4], alo[2][4];
#pragma unroll
            for (int mt = 0; mt < 2; ++mt) {
                uint32_t off = (uint32_t)(aRow0 + mt * 16) * 128 +
                               (uint32_t)(((kk * 2 + aKU) ^ aSw) << 4);
                LDSM4(ahi[mt], as + off);
                LDSM4(alo[mt], as + 16384 + off);
            }
#pragma unroll
            for (int half = 0; half < 2; ++half) {
                uint32_t bf[8][2];
#pragma unroll
                for (int p = 0; p < 4; ++p) {
                    uint32_t off = (uint32_t)(bN0 + half * 64 + p * 16) * 128 +
                                   (uint32_t)(((kk * 2 + bKU) ^ aSw) << 4);
                    uint32_t r[4];
                    LDSM4(r, bs + off);
                    bf[2 * p][0] = r[0]; bf[2 * p][1] = r[1];
                    bf[2 * p + 1][0] = r[2]; bf[2 * p + 1][1] = r[3];
                }
#pragma unroll
                for (int mt = 0; mt < 2; ++mt)
#pragma unroll
                    for (int q = 0; q < 8; ++q)
                        MMA(acc[mt][half * 8 + q], ahi[mt], bf[q]);
#pragma unroll
                for (int mt = 0; mt < 2; ++mt)
#pragma unroll
                    for (int q = 0; q < 8; ++q)
                        MMA(acc[mt][half * 8 + q], alo[mt], bf[q]);
            }
        }
        __syncthreads();
        buf ^= 1;
    }

    // ---- epilogue: stats partials + fp16 Y staged in dead B smem ----
    char* yst = smem + 8192;      // 64KB staging (B region, dead)
    float* st = (float*)smem;     // [8 warps][2 stats][128 cols]
    {
        const int rl = wr * 32 + (lane >> 2);
        const int cq = (lane & 3) * 2;
#pragma unroll
        for (int mt = 0; mt < 2; ++mt)
#pragma unroll
            for (int h = 0; h < 2; ++h) {
                const int row = rl + mt * 16 + h * 8;
                const uint32_t sw = (uint32_t)(row & 7) << 4;
#pragma unroll
                for (int nt = 0; nt < 16; ++nt) {
                    const int col = wc * 128 + nt * 8 + cq;
                    __half2 hv = __floats2half2_rn(acc[mt][nt][2 * h],
                                                   acc[mt][nt][2 * h + 1]);
                    *(__half2*)(yst + ((uint32_t)row * 512 + (((uint32_t)col * 2) ^ sw))) = hv;
                }
            }
    }
#pragma unroll
    for (int nt = 0; nt < 16; ++nt)
#pragma unroll
        for (int c = 0; c < 2; ++c) {
            float v0 = acc[0][nt][c],     v1 = acc[0][nt][2 + c];
            float v2 = acc[1][nt][c],     v3 = acc[1][nt][2 + c];
            float s  = (v0 + v1) + (v2 + v3);
            float s2 = fmaf(v0, v0, fmaf(v1, v1, fmaf(v2, v2, v3 * v3)));
#pragma unroll
            for (int m = 4; m <= 16; m <<= 1) {
                s  += __shfl_xor_sync(0xFFFFFFFF, s, m);
                s2 += __shfl_xor_sync(0xFFFFFFFF, s2, m);
            }
            if (lane < 4) {
                st[(wid * 2 + 0) * 128 + nt * 8 + lane * 2 + c] = s;
                st[(wid * 2 + 1) * 128 + nt * 8 + lane * 2 + c] = s2;
            }
        }
    __syncthreads();

    // coalesced fp16 Y copy-out (128 rows x 512B)
    {
        __half* yg = g_Yh + ((size_t)bg * 128 * 40 + n) * 256;
#pragma unroll
        for (int i = 0; i < 16; ++i) {
            int u = tid + 256 * i;
            int row = u >> 5, o = (u & 31) * 16;
            uint4 v = *(const uint4*)(yst + (uint32_t)row * 512 +
                                      ((uint32_t)o ^ ((uint32_t)(row & 7) << 4)));
            *(uint4*)((char*)(yg + (size_t)row * 40 * 256) + o) = v;
        }
    }
    // fold warp partials -> g_sp
    {
        const int col = tid;
        const int wch = col >> 7, ci = col & 127;
        float ts = 0.f, ts2 = 0.f;
#pragma unroll
        for (int w = 0; w < 4; ++w) {
            ts  += st[((w * 2 + wch) * 2 + 0) * 128 + ci];
            ts2 += st[((w * 2 + wch) * 2 + 1) * 128 + ci];
        }
        float* gp = g_sp + (size_t)(n * 64 + bg) * 512;
        gp[col] = ts;
        gp[256 + col] = ts2;
    }
}

// ---------------------------------------------------------------------------
// K3b1: partial fold over 8 bgs. K3b2: final scale/shift.
// ---------------------------------------------------------------------------
__global__ void k3b1_fold() {
    const int n = blockIdx.x, y = blockIdx.y, col = threadIdx.x;
    float s = 0.f, s2 = 0.f;
#pragma unroll
    for (int i = 0; i < 8; ++i) {
        const float* gp = g_sp + (size_t)(n * 64 + y * 8 + i) * 512;
        s += gp[col];
        s2 += gp[256 + col];
    }
    float* o = g_sp2 + (size_t)(n * 8 + y) * 512;
    o[col] = s;
    o[256 + col] = s2;
}

__global__ void k3b2_scaleshift(const float* __restrict__ gamma,
                                const float* __restrict__ beta) {
    const int n = blockIdx.x, col = threadIdx.x;
    float s = 0.f, s2 = 0.f;
#pragma unroll
    for (int y = 0; y < 8; ++y) {
        const float* gp = g_sp2 + (size_t)(n * 8 + y) * 512;
        s += gp[col];
        s2 += gp[256 + col];
    }
    const float inv = 1.f / (float)B_;
    float mean = s * inv;
    float var = fmaxf(s2 * inv - mean * mean, 0.f);
    int nf = n * 256 + col;
    int blk = n / 10;
    float sc = gamma[blk * NF + nf] * rsqrtf(var + 1e-5f);
    float bsum = beta[nf] + beta[NF + nf] + beta[2 * NF + nf] + beta[3 * NF + nf];
    g_scale[nf] = sc;
    g_shift[nf] = fmaf(-mean, sc, bsum);
}

// ---------------------------------------------------------------------------
// K4: out = Yh * scale + shift (fp16 read, fp32 write).
// ---------------------------------------------------------------------------
__global__ void k4_normalize(float* __restrict__ out) {
    const size_t gid = (size_t)blockIdx.x * blockDim.x + threadIdx.x;
    uint4 raw = ((const uint4*)g_Yh)[gid];
    const int col8 = (int)(gid & 31);
    const int grow = (int)(gid >> 5);
    const int n = grow % 40;
    const float* scp = g_scale + n * 256 + col8 * 8;
    const float* shp = g_shift + n * 256 + col8 * 8;
    float4 sc0 = *(const float4*)scp, sc1 = *(const float4*)(scp + 4);
    float4 sh0 = *(const float4*)shp, sh1 = *(const float4*)(shp + 4);
    const __half2* hp = (const __half2*)&raw;
    float2 f0 = __half22float2(hp[0]);
    float2 f1 = __half22float2(hp[1]);
    float2 f2 = __half22float2(hp[2]);
    float2 f3 = __half22float2(hp[3]);
    float4 o0, o1;
    o0.x = fmaf(f0.x, sc0.x, sh0.x);
    o0.y = fmaf(f0.y, sc0.y, sh0.y);
    o0.z = fmaf(f1.x, sc0.z, sh0.z);
    o0.w = fmaf(f1.y, sc0.w, sh0.w);
    o1.x = fmaf(f2.x, sc1.x, sh1.x);
    o1.y = fmaf(f2.y, sc1.y, sh1.y);
    o1.z = fmaf(f3.x, sc1.z, sh1.z);
    o1.w = fmaf(f3.y, sc1.w, sh1.w);
    float* op = out + (size_t)grow * 256 + col8 * 8;
    *(float4*)op = o0;
    *(float4*)(op + 4) = o1;
}

// ---------------------------------------------------------------------------
extern "C" void kernel_launch(void* const* d_in, const int* in_sizes, int n_in,
                              void* d_out, int out_size) {
    const float* input = (const float*)d_in[0];
    const float* adj   = (const float*)d_in[1];
    const float* W     = (const float*)d_in[2];
    const float* gamma = (const float*)d_in[3];
    const float* beta  = (const float*)d_in[4];
    float* out = (float*)d_out;

    static bool inited = false;
    static cudaStream_t s2;
    static cudaEvent_t ev0, ev2;
    if (!inited) {
        cudaFuncSetAttribute(k2_gemm_stats, cudaFuncAttributeMaxDynamicSharedMemorySize, SMEM_K2);
        int prLo, prHi;
        cudaDeviceGetStreamPriorityRange(&prLo, &prHi);   // prLo = lowest
        cudaStreamCreateWithPriority(&s2, cudaStreamNonBlocking, prLo);
        cudaEventCreateWithFlags(&ev0, cudaEventDisableTiming);
        cudaEventCreateWithFlags(&ev2, cudaEventDisableTiming);
        inited = true;
    }

    k0_wprep<<<256, 256>>>(W);                       // resets g_cnt first
    cudaEventRecord(ev0, 0);
    cudaStreamWaitEvent(s2, ev0, 0);
    k1_blockdiag<<<dim3(4, B_), 256>>>(input, adj);  // stream 0 (higher prio)
    k2_gemm_stats<<<dim3(40, 64), 256, SMEM_K2, s2>>>();  // low prio, spin-gated
    cudaEventRecord(ev2, s2);
    cudaStreamWaitEvent(0, ev2, 0);
    k3b1_fold<<<dim3(40, 8), 256>>>();
    k3b2_scaleshift<<<40, 256>>>(gamma, beta);
    k4_normalize<<<(TOT / 8) / 256, 256>>>(out);
}

// round 11
// speedup vs baseline: 1.3992x; 1.3992x over previous
#include <cuda_runtime.h>
#include <cuda_fp16.h>
#include <cstdint>

#define B_   8192
#define N_   40
#define F_   256
#define NF   10240
#define TOT  83886080

// ---------------- device scratch (no allocation allowed) --------------------
__device__ __align__(256) __half g_S[TOT];         // S = input @ W  (fp16)
__device__ __align__(256) __half g_Yh[TOT];        // Y = adjblk @ S (fp16)
__device__ __align__(256) __half g_Whi[F_ * F_];   // K-major [fout][fin]
__device__ float g_spY[4 * 64 * 2 * 2560];         // [i][bg][stat][r*256+f]
__device__ float g_scale[NF];
__device__ float g_shift[NF];

// ---------------- helpers ---------------------------------------------------
__device__ __forceinline__ uint32_t smem_u32(const void* p) {
    uint32_t a;
    asm("{ .reg .u64 t; cvta.to.shared.u64 t, %1; cvt.u32.u64 %0, t; }" : "=r"(a) : "l"(p));
    return a;
}
__device__ __forceinline__ void cp16(uint32_t dst, const void* src) {
    asm volatile("cp.async.cg.shared.global [%0], [%1], 16;" :: "r"(dst), "l"(src));
}
#define CP_COMMIT() asm volatile("cp.async.commit_group;" ::: "memory")
#define CP_WAIT(n)  asm volatile("cp.async.wait_group %0;" :: "n"(n) : "memory")

#define LDSM4(r, addr)                                                          \
    asm volatile("ldmatrix.sync.aligned.m8n8.x4.shared.b16 {%0,%1,%2,%3}, [%4];"\
        : "=r"((r)[0]), "=r"((r)[1]), "=r"((r)[2]), "=r"((r)[3]) : "r"(addr))

#define MMA(c, a, b)                                                            \
    asm volatile("mma.sync.aligned.m16n8k16.row.col.f32.f16.f16.f32 "           \
        "{%0,%1,%2,%3}, {%4,%5,%6,%7}, {%8,%9}, {%0,%1,%2,%3};"                 \
        : "+f"((c)[0]), "+f"((c)[1]), "+f"((c)[2]), "+f"((c)[3])                \
        : "r"((a)[0]), "r"((a)[1]), "r"((a)[2]), "r"((a)[3]),                   \
          "r"((b)[0]), "r"((b)[1]))

__device__ __forceinline__ uint32_t h2u(__half2 h) { return *(uint32_t*)&h; }

// ---------------------------------------------------------------------------
// K0: W [fin][fout] fp32 -> fp16 K-major [fout][fin]
// ---------------------------------------------------------------------------
__global__ void k0_wprep(const float* __restrict__ W) {
    int k = blockIdx.x, n = threadIdx.x;
    g_Whi[n * 256 + k] = __float2half_rn(W[k * 256 + n]);
}

// ---------------------------------------------------------------------------
// KS: S = input @ W, fp16-split 2-pass HMMA, input converted in-register.
// CTA = 128 contiguous global rows x all 256 cols. grid 2560.
// smem: [B resident 131072][A conv hi/lo double-buffer 2 x 32768] = 196608.
// ---------------------------------------------------------------------------
#define SMEM_KS 196608

__global__ __launch_bounds__(256, 1) void kS_gemm(const float* __restrict__ input) {
    extern __shared__ char smem[];
    const uint32_t sb = smem_u32(smem);
    const int tid = threadIdx.x, lane = tid & 31, wid = tid >> 5;
    const int wr = wid >> 1, wc = wid & 1;
    const size_t rowBase = (size_t)blockIdx.x * 128;

    // ---- resident B: [kcc 4][256 rows x 128B, swizzled] ----
    {
        const char* bB = (const char*)g_Whi;
#pragma unroll
        for (int it = 0; it < 32; ++it) {
            int u = it * 256 + tid;
            int kcc = u >> 11, r = (u >> 3) & 255, o = u & 7;
            size_t gb = (size_t)r * 512 + (size_t)kcc * 128 + o * 16;
            uint32_t so = (uint32_t)kcc * 32768 + r * 128 + ((o ^ (r & 7)) << 4);
            cp16(sb + so, bB + gb);
        }
        CP_COMMIT();
    }

    // ---- A path: LDG fp32 -> split fp16 hi/lo -> STS swizzled ----
    const int arow = tid >> 1;                 // 0..127
    const int ahalf = tid & 1;                 // covers floats [ahalf*32, +32)
    const float* asrc = input + (rowBase + arow) * 256 + ahalf * 32;
    char* aconv = smem + 131072;

    auto ldgA = [&](int kcc, float4* p) {
        const float4* s = (const float4*)(asrc + kcc * 64);
#pragma unroll
        for (int j = 0; j < 8; ++j) p[j] = s[j];
    };
    auto stsA = [&](int buf, const float4* p) {
        char* a0 = aconv + buf * 32768;
        const uint32_t rbase = (uint32_t)arow * 128;
#pragma unroll
        for (int jj = 0; jj < 4; ++jj) {
            float v[8] = {p[2 * jj].x, p[2 * jj].y, p[2 * jj].z, p[2 * jj].w,
                          p[2 * jj + 1].x, p[2 * jj + 1].y, p[2 * jj + 1].z, p[2 * jj + 1].w};
            __half h[8];
            __half l[8];
#pragma unroll
            for (int q = 0; q < 8; ++q) {
                h[q] = __float2half_rn(v[q]);
                l[q] = __float2half_rn(v[q] - __half2float(h[q]));
            }
            uint32_t off = rbase + ((uint32_t)((ahalf * 4 + jj) ^ (arow & 7)) << 4);
            uint4 uh, ul;
            uh.x = h2u(__halves2half2(h[0], h[1]));
            uh.y = h2u(__halves2half2(h[2], h[3]));
            uh.z = h2u(__halves2half2(h[4], h[5]));
            uh.w = h2u(__halves2half2(h[6], h[7]));
            ul.x = h2u(__halves2half2(l[0], l[1]));
            ul.y = h2u(__halves2half2(l[2], l[3]));
            ul.z = h2u(__halves2half2(l[4], l[5]));
            ul.w = h2u(__halves2half2(l[6], l[7]));
            *(uint4*)(a0 + off) = uh;
            *(uint4*)(a0 + 16384 + off) = ul;
        }
    };

    {
        float4 p0[8];
        ldgA(0, p0);
        stsA(0, p0);
    }
    CP_WAIT(0);          // B resident ready
    __syncthreads();

    float acc[2][16][4];
#pragma unroll
    for (int mt = 0; mt < 2; ++mt)
#pragma unroll
        for (int nt = 0; nt < 16; ++nt)
#pragma unroll
            for (int q = 0; q < 4; ++q) acc[mt][nt][q] = 0.f;

    const int aRow0 = wr * 32 + (lane & 15);
    const int aKU = lane >> 4;
    const int aSw = lane & 7;
    const int bN0 = wc * 128 + (lane & 7) + ((lane >> 4) & 1) * 8;
    const int bKU = (lane >> 3) & 1;

    int buf = 0;
#pragma unroll
    for (int kcc = 0; kcc < 4; ++kcc) {
        float4 pn[8];
        if (kcc < 3) ldgA(kcc + 1, pn);        // LDG in flight over MMA loop

        const uint32_t as = sb + 131072 + (uint32_t)buf * 32768;
        const uint32_t bs = sb + (uint32_t)kcc * 32768;
#pragma unroll
        for (int kk = 0; kk < 4; ++kk) {
            uint32_t ahi[2][4], alo[2][4];
#pragma unroll
            for (int mt = 0; mt < 2; ++mt) {
                uint32_t off = (uint32_t)(aRow0 + mt * 16) * 128 +
                               (uint32_t)(((kk * 2 + aKU) ^ aSw) << 4);
                LDSM4(ahi[mt], as + off);
                LDSM4(alo[mt], as + 16384 + off);
            }
#pragma unroll
            for (int half = 0; half < 2; ++half) {
                uint32_t bf[8][2];
#pragma unroll
                for (int p = 0; p < 4; ++p) {
                    uint32_t off = (uint32_t)(bN0 + half * 64 + p * 16) * 128 +
                                   (uint32_t)(((kk * 2 + bKU) ^ aSw) << 4);
                    uint32_t r[4];
                    LDSM4(r, bs + off);
                    bf[2 * p][0] = r[0]; bf[2 * p][1] = r[1];
                    bf[2 * p + 1][0] = r[2]; bf[2 * p + 1][1] = r[3];
                }
#pragma unroll
                for (int mt = 0; mt < 2; ++mt)
#pragma unroll
                    for (int q = 0; q < 8; ++q)
                        MMA(acc[mt][half * 8 + q], ahi[mt], bf[q]);
#pragma unroll
                for (int mt = 0; mt < 2; ++mt)
#pragma unroll
                    for (int q = 0; q < 8; ++q)
                        MMA(acc[mt][half * 8 + q], alo[mt], bf[q]);
            }
        }
        if (kcc < 3) stsA(buf ^ 1, pn);
        __syncthreads();
        buf ^= 1;
    }

    // ---- epilogue: stage fp16 S (swizzled, B region dead) -> coalesced out --
    char* yst = smem;
    {
        const int rl = wr * 32 + (lane >> 2);
        const int cq = (lane & 3) * 2;
#pragma unroll
        for (int mt = 0; mt < 2; ++mt)
#pragma unroll
            for (int h = 0; h < 2; ++h) {
                const int row = rl + mt * 16 + h * 8;
                const uint32_t sw = (uint32_t)(row & 7) << 4;
#pragma unroll
                for (int nt = 0; nt < 16; ++nt) {
                    const int col = wc * 128 + nt * 8 + cq;
                    __half2 hv = __floats2half2_rn(acc[mt][nt][2 * h],
                                                   acc[mt][nt][2 * h + 1]);
                    *(__half2*)(yst + ((uint32_t)row * 512 + (((uint32_t)col * 2) ^ sw))) = hv;
                }
            }
    }
    __syncthreads();
    {
        char* sg = (char*)g_S + rowBase * 512;
#pragma unroll
        for (int i = 0; i < 16; ++i) {
            int u = tid + 256 * i;
            int row = u >> 5, o = (u & 31) * 16;
            uint4 v = *(const uint4*)(yst + (uint32_t)row * 512 +
                                      ((uint32_t)o ^ ((uint32_t)(row & 7) << 4)));
            *(uint4*)(sg + (size_t)row * 512 + o) = v;
        }
    }
}

// ---------------------------------------------------------------------------
// KY: Y[b, s+r, f] = sum_c adj[b,s+r,s+c] * S[b,s+c,f]; fp16 Y out + stats.
// grid (4 blocks, 64 bgs of 128 batches), 256 threads (one per f).
// adj blocks for all 128 batches preloaded in smem (51.2 KB).
// ---------------------------------------------------------------------------
__global__ __launch_bounds__(256, 1) void kY_apply(const float* __restrict__ adj) {
    __shared__ float sadj[128][100];
    const int i = blockIdx.x, s = i * 10;
    const int bg = blockIdx.y;
    const int f = threadIdx.x;

    // preload adj blocks: 12800 floats, 50 per thread
    for (int u = f; u < 12800; u += 256) {
        int bi = u / 100, rc = u % 100;
        int b = bg * 128 + bi;
        sadj[bi][rc] = adj[((size_t)b * 40 + s + rc / 10) * 40 + s + rc % 10];
    }
    __syncthreads();

    float st[10], st2[10];
#pragma unroll
    for (int r = 0; r < 10; ++r) { st[r] = 0.f; st2[r] = 0.f; }

    for (int bi = 0; bi < 128; ++bi) {
        const int b = bg * 128 + bi;
        const __half* sp = g_S + ((size_t)b * 40 + s) * 256 + f;
        float x[10];
#pragma unroll
        for (int c = 0; c < 10; ++c) x[c] = __half2float(sp[c * 256]);
        __half* yp = g_Yh + ((size_t)b * 40 + s) * 256 + f;
#pragma unroll
        for (int r = 0; r < 10; ++r) {
            float y = 0.f;
#pragma unroll
            for (int c = 0; c < 10; ++c) y = fmaf(sadj[bi][r * 10 + c], x[c], y);
            yp[r * 256] = __float2half_rn(y);
            st[r] += y;
            st2[r] = fmaf(y, y, st2[r]);
        }
    }
    float* gp = g_spY + (size_t)(i * 64 + bg) * 5120;
#pragma unroll
    for (int r = 0; r < 10; ++r) {
        gp[r * 256 + f] = st[r];
        gp[2560 + r * 256 + f] = st2[r];
    }
}

// ---------------------------------------------------------------------------
// K3b: fold bg partials -> scale/shift. grid 40, 256 threads.
// ---------------------------------------------------------------------------
__global__ void k3b_scaleshift(const float* __restrict__ gamma,
                               const float* __restrict__ beta) {
    const int n = blockIdx.x, col = threadIdx.x;
    const int i = n / 10, r = n % 10;
    float s = 0.f, s2 = 0.f;
#pragma unroll 4
    for (int bg = 0; bg < 64; ++bg) {
        const float* gp = g_spY + (size_t)(i * 64 + bg) * 5120 + r * 256 + col;
        s += gp[0];
        s2 += gp[2560];
    }
    const float inv = 1.f / (float)B_;
    float mean = s * inv;
    float var = fmaxf(s2 * inv - mean * mean, 0.f);
    int nf = n * 256 + col;
    float sc = gamma[i * NF + nf] * rsqrtf(var + 1e-5f);
    float bsum = beta[nf] + beta[NF + nf] + beta[2 * NF + nf] + beta[3 * NF + nf];
    g_scale[nf] = sc;
    g_shift[nf] = fmaf(-mean, sc, bsum);
}

// ---------------------------------------------------------------------------
// K4: out = Yh * scale + shift (fp16 read, fp32 write). 8 elems/thread.
// ---------------------------------------------------------------------------
__global__ void k4_normalize(float* __restrict__ out) {
    const size_t gid = (size_t)blockIdx.x * blockDim.x + threadIdx.x;
    uint4 raw = ((const uint4*)g_Yh)[gid];
    const int col8 = (int)(gid & 31);
    const int grow = (int)(gid >> 5);
    const int n = grow % 40;
    const float* scp = g_scale + n * 256 + col8 * 8;
    const float* shp = g_shift + n * 256 + col8 * 8;
    float4 sc0 = *(const float4*)scp, sc1 = *(const float4*)(scp + 4);
    float4 sh0 = *(const float4*)shp, sh1 = *(const float4*)(shp + 4);
    const __half2* hp = (const __half2*)&raw;
    float2 f0 = __half22float2(hp[0]);
    float2 f1 = __half22float2(hp[1]);
    float2 f2 = __half22float2(hp[2]);
    float2 f3 = __half22float2(hp[3]);
    float4 o0, o1;
    o0.x = fmaf(f0.x, sc0.x, sh0.x);
    o0.y = fmaf(f0.y, sc0.y, sh0.y);
    o0.z = fmaf(f1.x, sc0.z, sh0.z);
    o0.w = fmaf(f1.y, sc0.w, sh0.w);
    o1.x = fmaf(f2.x, sc1.x, sh1.x);
    o1.y = fmaf(f2.y, sc1.y, sh1.y);
    o1.z = fmaf(f3.x, sc1.z, sh1.z);
    o1.w = fmaf(f3.y, sc1.w, sh1.w);
    float* op = out + (size_t)grow * 256 + col8 * 8;
    *(float4*)op = o0;
    *(float4*)(op + 4) = o1;
}

// ---------------------------------------------------------------------------
extern "C" void kernel_launch(void* const* d_in, const int* in_sizes, int n_in,
                              void* d_out, int out_size) {
    const float* input = (const float*)d_in[0];
    const float* adj   = (const float*)d_in[1];
    const float* W     = (const float*)d_in[2];
    const float* gamma = (const float*)d_in[3];
    const float* beta  = (const float*)d_in[4];
    float* out = (float*)d_out;

    static bool inited = false;
    if (!inited) {
        cudaFuncSetAttribute(kS_gemm, cudaFuncAttributeMaxDynamicSharedMemorySize, SMEM_KS);
        inited = true;
    }

    k0_wprep<<<256, 256>>>(W);
    kS_gemm<<<2560, 256, SMEM_KS>>>(input);
    kY_apply<<<dim3(4, 64), 256>>>(adj);
    k3b_scaleshift<<<40, 256>>>(gamma, beta);
    k4_normalize<<<(TOT / 8) / 256, 256>>>(out);
}

// round 12
// speedup vs baseline: 1.5818x; 1.1305x over previous
#include <cuda_runtime.h>
#include <cuda_fp16.h>
#include <cstdint>

#define B_   8192
#define N_   40
#define F_   256
#define NF   10240
#define TOT  83886080

// ---------------- device scratch (no allocation allowed) --------------------
__device__ __align__(256) __half g_S[TOT];         // S = input @ W  (fp16)
__device__ __align__(256) __half g_Yh[TOT];        // Y = adjblk @ S (fp16)
__device__ __align__(256) __half g_Whi[F_ * F_];   // K-major [fout][fin]
__device__ float g_spY[4 * 64 * 2 * 2560];         // [i][bg][stat][r*256+f]
__device__ float g_spY2[40 * 8 * 2 * 256];         // [n][y][stat][col]
__device__ float g_scale[NF];
__device__ float g_shift[NF];

// ---------------- helpers ---------------------------------------------------
__device__ __forceinline__ uint32_t smem_u32(const void* p) {
    uint32_t a;
    asm("{ .reg .u64 t; cvta.to.shared.u64 t, %1; cvt.u32.u64 %0, t; }" : "=r"(a) : "l"(p));
    return a;
}
__device__ __forceinline__ void cp16(uint32_t dst, const void* src) {
    asm volatile("cp.async.cg.shared.global [%0], [%1], 16;" :: "r"(dst), "l"(src));
}
#define CP_COMMIT() asm volatile("cp.async.commit_group;" ::: "memory")
#define CP_WAIT(n)  asm volatile("cp.async.wait_group %0;" :: "n"(n) : "memory")

#define LDSM4(r, addr)                                                          \
    asm volatile("ldmatrix.sync.aligned.m8n8.x4.shared.b16 {%0,%1,%2,%3}, [%4];"\
        : "=r"((r)[0]), "=r"((r)[1]), "=r"((r)[2]), "=r"((r)[3]) : "r"(addr))

#define MMA(c, a, b)                                                            \
    asm volatile("mma.sync.aligned.m16n8k16.row.col.f32.f16.f16.f32 "           \
        "{%0,%1,%2,%3}, {%4,%5,%6,%7}, {%8,%9}, {%0,%1,%2,%3};"                 \
        : "+f"((c)[0]), "+f"((c)[1]), "+f"((c)[2]), "+f"((c)[3])                \
        : "r"((a)[0]), "r"((a)[1]), "r"((a)[2]), "r"((a)[3]),                   \
          "r"((b)[0]), "r"((b)[1]))

__device__ __forceinline__ uint32_t h2u(__half2 h) { return *(uint32_t*)&h; }

// ---------------------------------------------------------------------------
// K0: W [fin][fout] fp32 -> fp16 K-major [fout][fin]
// ---------------------------------------------------------------------------
__global__ void k0_wprep(const float* __restrict__ W) {
    int k = blockIdx.x, n = threadIdx.x;
    g_Whi[n * 256 + k] = __float2half_rn(W[k * 256 + n]);
}

// ---------------------------------------------------------------------------
// KS: S = input @ W, single-pass fp16 HMMA; input converted in-register.
// CTA = 128 contiguous global rows x all 256 cols. grid 2560.
// smem: [B resident 131072][A fp16 double-buffer 2 x 16384] = 163840.
// ---------------------------------------------------------------------------
#define SMEM_KS 163840

__global__ __launch_bounds__(256, 1) void kS_gemm(const float* __restrict__ input) {
    extern __shared__ char smem[];
    const uint32_t sb = smem_u32(smem);
    const int tid = threadIdx.x, lane = tid & 31, wid = tid >> 5;
    const int wr = wid >> 1, wc = wid & 1;
    const size_t rowBase = (size_t)blockIdx.x * 128;

    // ---- resident B: [kcc 4][256 rows x 128B, swizzled] ----
    {
        const char* bB = (const char*)g_Whi;
#pragma unroll
        for (int it = 0; it < 32; ++it) {
            int u = it * 256 + tid;
            int kcc = u >> 11, r = (u >> 3) & 255, o = u & 7;
            size_t gb = (size_t)r * 512 + (size_t)kcc * 128 + o * 16;
            uint32_t so = (uint32_t)kcc * 32768 + r * 128 + ((o ^ (r & 7)) << 4);
            cp16(sb + so, bB + gb);
        }
        CP_COMMIT();
    }

    // ---- A path: LDG fp32 -> fp16 -> STS swizzled (single component) ----
    const int arow = tid >> 1;                 // 0..127
    const int ahalf = tid & 1;                 // floats [ahalf*32, +32)
    const float* asrc = input + (rowBase + arow) * 256 + ahalf * 32;
    char* aconv = smem + 131072;

    auto ldgA = [&](int kcc, float4* p) {
        const float4* s = (const float4*)(asrc + kcc * 64);
#pragma unroll
        for (int j = 0; j < 8; ++j) p[j] = s[j];
    };
    auto stsA = [&](int buf, const float4* p) {
        char* a0 = aconv + buf * 16384;
        const uint32_t rbase = (uint32_t)arow * 128;
#pragma unroll
        for (int jj = 0; jj < 4; ++jj) {
            float v[8] = {p[2 * jj].x, p[2 * jj].y, p[2 * jj].z, p[2 * jj].w,
                          p[2 * jj + 1].x, p[2 * jj + 1].y, p[2 * jj + 1].z, p[2 * jj + 1].w};
            uint32_t off = rbase + ((uint32_t)((ahalf * 4 + jj) ^ (arow & 7)) << 4);
            uint4 uh;
            uh.x = h2u(__floats2half2_rn(v[0], v[1]));
            uh.y = h2u(__floats2half2_rn(v[2], v[3]));
            uh.z = h2u(__floats2half2_rn(v[4], v[5]));
            uh.w = h2u(__floats2half2_rn(v[6], v[7]));
            *(uint4*)(a0 + off) = uh;
        }
    };

    {
        float4 p0[8];
        ldgA(0, p0);
        stsA(0, p0);
    }
    CP_WAIT(0);          // B resident ready
    __syncthreads();

    float acc[2][16][4];
#pragma unroll
    for (int mt = 0; mt < 2; ++mt)
#pragma unroll
        for (int nt = 0; nt < 16; ++nt)
#pragma unroll
            for (int q = 0; q < 4; ++q) acc[mt][nt][q] = 0.f;

    const int aRow0 = wr * 32 + (lane & 15);
    const int aKU = lane >> 4;
    const int aSw = lane & 7;
    const int bN0 = wc * 128 + (lane & 7) + ((lane >> 4) & 1) * 8;
    const int bKU = (lane >> 3) & 1;

    int buf = 0;
#pragma unroll
    for (int kcc = 0; kcc < 4; ++kcc) {
        float4 pn[8];
        if (kcc < 3) ldgA(kcc + 1, pn);        // LDG in flight over MMA loop

        const uint32_t as = sb + 131072 + (uint32_t)buf * 16384;
        const uint32_t bs = sb + (uint32_t)kcc * 32768;
#pragma unroll
        for (int kk = 0; kk < 4; ++kk) {
            uint32_t ahi[2][4];
#pragma unroll
            for (int mt = 0; mt < 2; ++mt) {
                uint32_t off = (uint32_t)(aRow0 + mt * 16) * 128 +
                               (uint32_t)(((kk * 2 + aKU) ^ aSw) << 4);
                LDSM4(ahi[mt], as + off);
            }
#pragma unroll
            for (int half = 0; half < 2; ++half) {
                uint32_t bf[8][2];
#pragma unroll
                for (int p = 0; p < 4; ++p) {
                    uint32_t off = (uint32_t)(bN0 + half * 64 + p * 16) * 128 +
                                   (uint32_t)(((kk * 2 + bKU) ^ aSw) << 4);
                    uint32_t r[4];
                    LDSM4(r, bs + off);
                    bf[2 * p][0] = r[0]; bf[2 * p][1] = r[1];
                    bf[2 * p + 1][0] = r[2]; bf[2 * p + 1][1] = r[3];
                }
#pragma unroll
                for (int mt = 0; mt < 2; ++mt)
#pragma unroll
                    for (int q = 0; q < 8; ++q)
                        MMA(acc[mt][half * 8 + q], ahi[mt], bf[q]);
            }
        }
        if (kcc < 3) stsA(buf ^ 1, pn);
        __syncthreads();
        buf ^= 1;
    }

    // ---- epilogue: stage fp16 S (swizzled, B region dead) -> coalesced out --
    char* yst = smem;
    {
        const int rl = wr * 32 + (lane >> 2);
        const int cq = (lane & 3) * 2;
#pragma unroll
        for (int mt = 0; mt < 2; ++mt)
#pragma unroll
            for (int h = 0; h < 2; ++h) {
                const int row = rl + mt * 16 + h * 8;
                const uint32_t sw = (uint32_t)(row & 7) << 4;
#pragma unroll
                for (int nt = 0; nt < 16; ++nt) {
                    const int col = wc * 128 + nt * 8 + cq;
                    __half2 hv = __floats2half2_rn(acc[mt][nt][2 * h],
                                                   acc[mt][nt][2 * h + 1]);
                    *(__half2*)(yst + ((uint32_t)row * 512 + (((uint32_t)col * 2) ^ sw))) = hv;
                }
            }
    }
    __syncthreads();
    {
        char* sg = (char*)g_S + rowBase * 512;
#pragma unroll
        for (int i = 0; i < 16; ++i) {
            int u = tid + 256 * i;
            int row = u >> 5, o = (u & 31) * 16;
            uint4 v = *(const uint4*)(yst + (uint32_t)row * 512 +
                                      ((uint32_t)o ^ ((uint32_t)(row & 7) << 4)));
            *(uint4*)(sg + (size_t)row * 512 + o) = v;
        }
    }
}

// ---------------------------------------------------------------------------
// KY: Y[b, s+r, f] = sum_c adj[b,s+r,s+c] * S[b,s+c,f]; fp16 Y out + stats.
// grid (4 blocks, 64 bgs of 128 batches), 256 threads (one per f).
// ---------------------------------------------------------------------------
__global__ __launch_bounds__(256, 1) void kY_apply(const float* __restrict__ adj) {
    __shared__ float sadj[128][100];
    const int i = blockIdx.x, s = i * 10;
    const int bg = blockIdx.y;
    const int f = threadIdx.x;

    for (int u = f; u < 12800; u += 256) {
        int bi = u / 100, rc = u % 100;
        int b = bg * 128 + bi;
        sadj[bi][rc] = adj[((size_t)b * 40 + s + rc / 10) * 40 + s + rc % 10];
    }
    __syncthreads();

    float st[10], st2[10];
#pragma unroll
    for (int r = 0; r < 10; ++r) { st[r] = 0.f; st2[r] = 0.f; }

    for (int bi = 0; bi < 128; ++bi) {
        const int b = bg * 128 + bi;
        const __half* sp = g_S + ((size_t)b * 40 + s) * 256 + f;
        float x[10];
#pragma unroll
        for (int c = 0; c < 10; ++c) x[c] = __half2float(sp[c * 256]);
        __half* yp = g_Yh + ((size_t)b * 40 + s) * 256 + f;
#pragma unroll
        for (int r = 0; r < 10; ++r) {
            float y = 0.f;
#pragma unroll
            for (int c = 0; c < 10; ++c) y = fmaf(sadj[bi][r * 10 + c], x[c], y);
            yp[r * 256] = __float2half_rn(y);
            st[r] += y;
            st2[r] = fmaf(y, y, st2[r]);
        }
    }
    float* gp = g_spY + (size_t)(i * 64 + bg) * 5120;
#pragma unroll
    for (int r = 0; r < 10; ++r) {
        gp[r * 256 + f] = st[r];
        gp[2560 + r * 256 + f] = st2[r];
    }
}

// ---------------------------------------------------------------------------
// K3b1: fold 8 bgs per group. grid (40, 8), 256 threads.
// ---------------------------------------------------------------------------
__global__ void k3b1_fold() {
    const int n = blockIdx.x, y = blockIdx.y, col = threadIdx.x;
    const int i = n / 10, r = n % 10;
    float s = 0.f, s2 = 0.f;
#pragma unroll
    for (int j = 0; j < 8; ++j) {
        const float* gp = g_spY + (size_t)(i * 64 + y * 8 + j) * 5120 + r * 256 + col;
        s += gp[0];
        s2 += gp[2560];
    }
    float* o = g_spY2 + (size_t)(n * 8 + y) * 512;
    o[col] = s;
    o[256 + col] = s2;
}

// K3b2: final fold -> scale/shift. grid 40, 256 threads.
__global__ void k3b2_scaleshift(const float* __restrict__ gamma,
                                const float* __restrict__ beta) {
    const int n = blockIdx.x, col = threadIdx.x;
    const int i = n / 10;
    float s = 0.f, s2 = 0.f;
#pragma unroll
    for (int y = 0; y < 8; ++y) {
        const float* gp = g_spY2 + (size_t)(n * 8 + y) * 512;
        s += gp[col];
        s2 += gp[256 + col];
    }
    const float inv = 1.f / (float)B_;
    float mean = s * inv;
    float var = fmaxf(s2 * inv - mean * mean, 0.f);
    int nf = n * 256 + col;
    float sc = gamma[i * NF + nf] * rsqrtf(var + 1e-5f);
    float bsum = beta[nf] + beta[NF + nf] + beta[2 * NF + nf] + beta[3 * NF + nf];
    g_scale[nf] = sc;
    g_shift[nf] = fmaf(-mean, sc, bsum);
}

// ---------------------------------------------------------------------------
// K4: out = Yh * scale + shift (fp16 read, fp32 write). 8 elems/thread.
// ---------------------------------------------------------------------------
__global__ void k4_normalize(float* __restrict__ out) {
    const size_t gid = (size_t)blockIdx.x * blockDim.x + threadIdx.x;
    uint4 raw = ((const uint4*)g_Yh)[gid];
    const int col8 = (int)(gid & 31);
    const int grow = (int)(gid >> 5);
    const int n = grow % 40;
    const float* scp = g_scale + n * 256 + col8 * 8;
    const float* shp = g_shift + n * 256 + col8 * 8;
    float4 sc0 = *(const float4*)scp, sc1 = *(const float4*)(scp + 4);
    float4 sh0 = *(const float4*)shp, sh1 = *(const float4*)(shp + 4);
    const __half2* hp = (const __half2*)&raw;
    float2 f0 = __half22float2(hp[0]);
    float2 f1 = __half22float2(hp[1]);
    float2 f2 = __half22float2(hp[2]);
    float2 f3 = __half22float2(hp[3]);
    float4 o0, o1;
    o0.x = fmaf(f0.x, sc0.x, sh0.x);
    o0.y = fmaf(f0.y, sc0.y, sh0.y);
    o0.z = fmaf(f1.x, sc0.z, sh0.z);
    o0.w = fmaf(f1.y, sc0.w, sh0.w);
    o1.x = fmaf(f2.x, sc1.x, sh1.x);
    o1.y = fmaf(f2.y, sc1.y, sh1.y);
    o1.z = fmaf(f3.x, sc1.z, sh1.z);
    o1.w = fmaf(f3.y, sc1.w, sh1.w);
    float* op = out + (size_t)grow * 256 + col8 * 8;
    *(float4*)op = o0;
    *(float4*)(op + 4) = o1;
}

// ---------------------------------------------------------------------------
extern "C" void kernel_launch(void* const* d_in, const int* in_sizes, int n_in,
                              void* d_out, int out_size) {
    const float* input = (const float*)d_in[0];
    const float* adj   = (const float*)d_in[1];
    const float* W     = (const float*)d_in[2];
    const float* gamma = (const float*)d_in[3];
    const float* beta  = (const float*)d_in[4];
    float* out = (float*)d_out;

    static bool inited = false;
    if (!inited) {
        cudaFuncSetAttribute(kS_gemm, cudaFuncAttributeMaxDynamicSharedMemorySize, SMEM_KS);
        inited = true;
    }

    k0_wprep<<<256, 256>>>(W);
    kS_gemm<<<2560, 256, SMEM_KS>>>(input);
    kY_apply<<<dim3(4, 64), 256>>>(adj);
    k3b1_fold<<<dim3(40, 8), 256>>>();
    k3b2_scaleshift<<<40, 256>>>(gamma, beta);
    k4_normalize<<<(TOT / 8) / 256, 256>>>(out);
}

// round 13
// speedup vs baseline: 1.7863x; 1.1293x over previous
#include <cuda_runtime.h>
#include <cuda_fp16.h>
#include <cstdint>

#define B_   8192
#define N_   40
#define F_   256
#define NF   10240
#define TOT  83886080

// ---------------- device scratch (no allocation allowed) --------------------
__device__ __align__(256) __half g_S[TOT];         // S = input @ W  (fp16)
__device__ __align__(256) __half g_Yh[TOT];        // Y = adjblk @ S (fp16)
__device__ __align__(256) __half g_Whi[F_ * F_];   // K-major [fout][fin]
__device__ float g_spY[4 * 64 * 2 * 2560];         // [i][bg][stat][r*256+f]
__device__ float g_spY2[40 * 8 * 2 * 256];         // [n][y][stat][col]
__device__ float g_scale[NF];
__device__ float g_shift[NF];

// ---------------- helpers ---------------------------------------------------
__device__ __forceinline__ uint32_t smem_u32(const void* p) {
    uint32_t a;
    asm("{ .reg .u64 t; cvta.to.shared.u64 t, %1; cvt.u32.u64 %0, t; }" : "=r"(a) : "l"(p));
    return a;
}
__device__ __forceinline__ void cp16(uint32_t dst, const void* src) {
    asm volatile("cp.async.cg.shared.global [%0], [%1], 16;" :: "r"(dst), "l"(src));
}
#define CP_COMMIT() asm volatile("cp.async.commit_group;" ::: "memory")
#define CP_WAIT(n)  asm volatile("cp.async.wait_group %0;" :: "n"(n) : "memory")

#define LDSM4(r, addr)                                                          \
    asm volatile("ldmatrix.sync.aligned.m8n8.x4.shared.b16 {%0,%1,%2,%3}, [%4];"\
        : "=r"((r)[0]), "=r"((r)[1]), "=r"((r)[2]), "=r"((r)[3]) : "r"(addr))

#define MMA(c, a, b)                                                            \
    asm volatile("mma.sync.aligned.m16n8k16.row.col.f32.f16.f16.f32 "           \
        "{%0,%1,%2,%3}, {%4,%5,%6,%7}, {%8,%9}, {%0,%1,%2,%3};"                 \
        : "+f"((c)[0]), "+f"((c)[1]), "+f"((c)[2]), "+f"((c)[3])                \
        : "r"((a)[0]), "r"((a)[1]), "r"((a)[2]), "r"((a)[3]),                   \
          "r"((b)[0]), "r"((b)[1]))

__device__ __forceinline__ uint32_t h2u(__half2 h) { return *(uint32_t*)&h; }

// ---------------------------------------------------------------------------
// K0: W [fin][fout] fp32 -> fp16 K-major [fout][fin]
// ---------------------------------------------------------------------------
__global__ void k0_wprep(const float* __restrict__ W) {
    int k = blockIdx.x, n = threadIdx.x;
    g_Whi[n * 256 + k] = __float2half_rn(W[k * 256 + n]);
}

// ---------------------------------------------------------------------------
// KS: S = input @ W, single-pass fp16 HMMA; input staged through smem fp32
// then converted to fp16 (no long-lived registers -> no spills).
// CTA = 128 contiguous global rows x all 256 cols. grid 2560.
// smem: [B resident 131072][F fp32 stage 32768][H fp16 2 x 16384] = 196608.
// ---------------------------------------------------------------------------
#define SMEM_KS 196608
#define SM_F 131072
#define SM_H 163840

__global__ __launch_bounds__(256, 1) void kS_gemm(const float* __restrict__ input) {
    extern __shared__ char smem[];
    const uint32_t sb = smem_u32(smem);
    const int tid = threadIdx.x, lane = tid & 31, wid = tid >> 5;
    const int wr = wid >> 1, wc = wid & 1;
    const size_t rowBase = (size_t)blockIdx.x * 128;

    // ---- resident B: [kcc 4][256 rows x 128B, swizzled] ----
    {
        const char* bB = (const char*)g_Whi;
#pragma unroll
        for (int it = 0; it < 32; ++it) {
            int u = it * 256 + tid;
            int kcc = u >> 11, r = (u >> 3) & 255, o = u & 7;
            size_t gb = (size_t)r * 512 + (size_t)kcc * 128 + o * 16;
            uint32_t so = (uint32_t)kcc * 32768 + r * 128 + ((o ^ (r & 7)) << 4);
            cp16(sb + so, bB + gb);
        }
    }

    // ---- A path: cp.async fp32 -> F, convert F -> H (swizzled fp16) ----
    auto loadF = [&](int kcc) {
#pragma unroll
        for (int it = 0; it < 8; ++it) {
            int u = it * 256 + tid;                 // 0..2047 16B units
            int row = u >> 4, o = u & 15;
            const char* src = (const char*)(input + (rowBase + row) * 256 +
                                            (size_t)kcc * 64 + o * 4);
            cp16(sb + SM_F + (uint32_t)u * 16, src);
        }
    };
    auto convertF = [&](int hbuf) {
        char* hb = smem + SM_H + hbuf * 16384;
#pragma unroll
        for (int it = 0; it < 8; ++it) {
            int u = it * 256 + tid;
            int row = u >> 4, o = u & 15;
            float4 v = *(const float4*)(smem + SM_F + (size_t)u * 16);
            uint2 w;
            w.x = h2u(__floats2half2_rn(v.x, v.y));
            w.y = h2u(__floats2half2_rn(v.z, v.w));
            *(uint2*)(hb + (uint32_t)row * 128 +
                      ((((uint32_t)o >> 1) ^ (uint32_t)(row & 7)) << 4) +
                      (uint32_t)(o & 1) * 8) = w;
        }
    };

    loadF(0);
    CP_COMMIT();          // group: B + F0
    CP_WAIT(0);
    __syncthreads();
    convertF(0);
    __syncthreads();
    loadF(1);
    CP_COMMIT();

    float acc[2][16][4];
#pragma unroll
    for (int mt = 0; mt < 2; ++mt)
#pragma unroll
        for (int nt = 0; nt < 16; ++nt)
#pragma unroll
            for (int q = 0; q < 4; ++q) acc[mt][nt][q] = 0.f;

    const int aRow0 = wr * 32 + (lane & 15);
    const int aKU = lane >> 4;
    const int aSw = lane & 7;
    const int bN0 = wc * 128 + (lane & 7) + ((lane >> 4) & 1) * 8;
    const int bKU = (lane >> 3) & 1;

#pragma unroll
    for (int kcc = 0; kcc < 4; ++kcc) {
        const uint32_t as = sb + SM_H + (uint32_t)(kcc & 1) * 16384;
        const uint32_t bs = sb + (uint32_t)kcc * 32768;
#pragma unroll
        for (int kk = 0; kk < 4; ++kk) {
            uint32_t ahi[2][4];
#pragma unroll
            for (int mt = 0; mt < 2; ++mt) {
                uint32_t off = (uint32_t)(aRow0 + mt * 16) * 128 +
                               (uint32_t)(((kk * 2 + aKU) ^ aSw) << 4);
                LDSM4(ahi[mt], as + off);
            }
#pragma unroll
            for (int half = 0; half < 2; ++half) {
                uint32_t bf[8][2];
#pragma unroll
                for (int p = 0; p < 4; ++p) {
                    uint32_t off = (uint32_t)(bN0 + half * 64 + p * 16) * 128 +
                                   (uint32_t)(((kk * 2 + bKU) ^ aSw) << 4);
                    uint32_t r[4];
                    LDSM4(r, bs + off);
                    bf[2 * p][0] = r[0]; bf[2 * p][1] = r[1];
                    bf[2 * p + 1][0] = r[2]; bf[2 * p + 1][1] = r[3];
                }
#pragma unroll
                for (int mt = 0; mt < 2; ++mt)
#pragma unroll
                    for (int q = 0; q < 8; ++q)
                        MMA(acc[mt][half * 8 + q], ahi[mt], bf[q]);
            }
        }
        if (kcc < 3) {
            CP_WAIT(0);                    // F(kcc+1) landed
            __syncthreads();               // also: all warps done with H(kcc^1)
            convertF((kcc + 1) & 1);
            __syncthreads();
            if (kcc < 2) {
                loadF(kcc + 2);
                CP_COMMIT();
            }
        }
    }

    // ---- epilogue: stage fp16 S (swizzled, B region dead) -> coalesced out --
    __syncthreads();
    char* yst = smem;
    {
        const int rl = wr * 32 + (lane >> 2);
        const int cq = (lane & 3) * 2;
#pragma unroll
        for (int mt = 0; mt < 2; ++mt)
#pragma unroll
            for (int h = 0; h < 2; ++h) {
                const int row = rl + mt * 16 + h * 8;
                const uint32_t sw = (uint32_t)(row & 7) << 4;
#pragma unroll
                for (int nt = 0; nt < 16; ++nt) {
                    const int col = wc * 128 + nt * 8 + cq;
                    __half2 hv = __floats2half2_rn(acc[mt][nt][2 * h],
                                                   acc[mt][nt][2 * h + 1]);
                    *(__half2*)(yst + ((uint32_t)row * 512 + (((uint32_t)col * 2) ^ sw))) = hv;
                }
            }
    }
    __syncthreads();
    {
        char* sg = (char*)g_S + rowBase * 512;
#pragma unroll
        for (int i = 0; i < 16; ++i) {
            int u = tid + 256 * i;
            int row = u >> 5, o = (u & 31) * 16;
            uint4 v = *(const uint4*)(yst + (uint32_t)row * 512 +
                                      ((uint32_t)o ^ ((uint32_t)(row & 7) << 4)));
            *(uint4*)(sg + (size_t)row * 512 + o) = v;
        }
    }
}

// ---------------------------------------------------------------------------
// KY: Y[b, s+r, f] = sum_c adj[b,s+r,s+c] * S[b,s+c,f]; fp16 Y out + stats.
// grid (4 blocks, 64 bgs of 128 batches), 256 threads (one per f).
// ---------------------------------------------------------------------------
__global__ __launch_bounds__(256, 1) void kY_apply(const float* __restrict__ adj) {
    __shared__ float sadj[128][100];
    const int i = blockIdx.x, s = i * 10;
    const int bg = blockIdx.y;
    const int f = threadIdx.x;

    for (int u = f; u < 12800; u += 256) {
        int bi = u / 100, rc = u % 100;
        int b = bg * 128 + bi;
        sadj[bi][rc] = adj[((size_t)b * 40 + s + rc / 10) * 40 + s + rc % 10];
    }
    __syncthreads();

    float st[10], st2[10];
#pragma unroll
    for (int r = 0; r < 10; ++r) { st[r] = 0.f; st2[r] = 0.f; }

    for (int bi = 0; bi < 128; ++bi) {
        const int b = bg * 128 + bi;
        const __half* sp = g_S + ((size_t)b * 40 + s) * 256 + f;
        float x[10];
#pragma unroll
        for (int c = 0; c < 10; ++c) x[c] = __half2float(sp[c * 256]);
        __half* yp = g_Yh + ((size_t)b * 40 + s) * 256 + f;
#pragma unroll
        for (int r = 0; r < 10; ++r) {
            float y = 0.f;
#pragma unroll
            for (int c = 0; c < 10; ++c) y = fmaf(sadj[bi][r * 10 + c], x[c], y);
            yp[r * 256] = __float2half_rn(y);
            st[r] += y;
            st2[r] = fmaf(y, y, st2[r]);
        }
    }
    float* gp = g_spY + (size_t)(i * 64 + bg) * 5120;
#pragma unroll
    for (int r = 0; r < 10; ++r) {
        gp[r * 256 + f] = st[r];
        gp[2560 + r * 256 + f] = st2[r];
    }
}

// ---------------------------------------------------------------------------
// K3b1: fold 8 bgs per group. grid (40, 8), 256 threads.
// ---------------------------------------------------------------------------
__global__ void k3b1_fold() {
    const int n = blockIdx.x, y = blockIdx.y, col = threadIdx.x;
    const int i = n / 10, r = n % 10;
    float s = 0.f, s2 = 0.f;
#pragma unroll
    for (int j = 0; j < 8; ++j) {
        const float* gp = g_spY + (size_t)(i * 64 + y * 8 + j) * 5120 + r * 256 + col;
        s += gp[0];
        s2 += gp[2560];
    }
    float* o = g_spY2 + (size_t)(n * 8 + y) * 512;
    o[col] = s;
    o[256 + col] = s2;
}

// K3b2: final fold -> scale/shift. grid 40, 256 threads.
__global__ void k3b2_scaleshift(const float* __restrict__ gamma,
                                const float* __restrict__ beta) {
    const int n = blockIdx.x, col = threadIdx.x;
    const int i = n / 10;
    float s = 0.f, s2 = 0.f;
#pragma unroll
    for (int y = 0; y < 8; ++y) {
        const float* gp = g_spY2 + (size_t)(n * 8 + y) * 512;
        s += gp[col];
        s2 += gp[256 + col];
    }
    const float inv = 1.f / (float)B_;
    float mean = s * inv;
    float var = fmaxf(s2 * inv - mean * mean, 0.f);
    int nf = n * 256 + col;
    float sc = gamma[i * NF + nf] * rsqrtf(var + 1e-5f);
    float bsum = beta[nf] + beta[NF + nf] + beta[2 * NF + nf] + beta[3 * NF + nf];
    g_scale[nf] = sc;
    g_shift[nf] = fmaf(-mean, sc, bsum);
}

// ---------------------------------------------------------------------------
// K4: out = Yh * scale + shift (fp16 read, fp32 write). 8 elems/thread.
// ---------------------------------------------------------------------------
__global__ void k4_normalize(float* __restrict__ out) {
    const size_t gid = (size_t)blockIdx.x * blockDim.x + threadIdx.x;
    uint4 raw = ((const uint4*)g_Yh)[gid];
    const int col8 = (int)(gid & 31);
    const int grow = (int)(gid >> 5);
    const int n = grow % 40;
    const float* scp = g_scale + n * 256 + col8 * 8;
    const float* shp = g_shift + n * 256 + col8 * 8;
    float4 sc0 = *(const float4*)scp, sc1 = *(const float4*)(scp + 4);
    float4 sh0 = *(const float4*)shp, sh1 = *(const float4*)(shp + 4);
    const __half2* hp = (const __half2*)&raw;
    float2 f0 = __half22float2(hp[0]);
    float2 f1 = __half22float2(hp[1]);
    float2 f2 = __half22float2(hp[2]);
    float2 f3 = __half22float2(hp[3]);
    float4 o0, o1;
    o0.x = fmaf(f0.x, sc0.x, sh0.x);
    o0.y = fmaf(f0.y, sc0.y, sh0.y);
    o0.z = fmaf(f1.x, sc0.z, sh0.z);
    o0.w = fmaf(f1.y, sc0.w, sh0.w);
    o1.x = fmaf(f2.x, sc1.x, sh1.x);
    o1.y = fmaf(f2.y, sc1.y, sh1.y);
    o1.z = fmaf(f3.x, sc1.z, sh1.z);
    o1.w = fmaf(f3.y, sc1.w, sh1.w);
    float* op = out + (size_t)grow * 256 + col8 * 8;
    *(float4*)op = o0;
    *(float4*)(op + 4) = o1;
}

// ---------------------------------------------------------------------------
extern "C" void kernel_launch(void* const* d_in, const int* in_sizes, int n_in,
                              void* d_out, int out_size) {
    const float* input = (const float*)d_in[0];
    const float* adj   = (const float*)d_in[1];
    const float* W     = (const float*)d_in[2];
    const float* gamma = (const float*)d_in[3];
    const float* beta  = (const float*)d_in[4];
    float* out = (float*)d_out;

    static bool inited = false;
    if (!inited) {
        cudaFuncSetAttribute(kS_gemm, cudaFuncAttributeMaxDynamicSharedMemorySize, SMEM_KS);
        inited = true;
    }

    k0_wprep<<<256, 256>>>(W);
    kS_gemm<<<2560, 256, SMEM_KS>>>(input);
    kY_apply<<<dim3(4, 64), 256>>>(adj);
    k3b1_fold<<<dim3(40, 8), 256>>>();
    k3b2_scaleshift<<<40, 256>>>(gamma, beta);
    k4_normalize<<<(TOT / 8) / 256, 256>>>(out);
}

// round 15
// speedup vs baseline: 1.8079x; 1.0121x over previous
#include <cuda_runtime.h>
#include <cuda_fp16.h>
#include <cstdint>

#define B_   8192
#define N_   40
#define F_   256
#define NF   10240
#define TOT  83886080

// ---------------- device scratch (no allocation allowed) --------------------
__device__ __align__(256) __half g_S[TOT];         // S = input @ W  (fp16)
__device__ __align__(256) __half g_Yh[TOT];        // Y = adjblk @ S (fp16)
__device__ __align__(256) __half g_Whi[F_ * F_];   // K-major [fout][fin]
__device__ float g_spY[4 * 64 * 2 * 2560];         // [i][bg][stat][r*256+f]
__device__ float g_spY2[40 * 8 * 2 * 256];         // [n][y][stat][col]
__device__ float g_scale[NF];
__device__ float g_shift[NF];

// ---------------- helpers ---------------------------------------------------
__device__ __forceinline__ uint32_t smem_u32(const void* p) {
    uint32_t a;
    asm("{ .reg .u64 t; cvta.to.shared.u64 t, %1; cvt.u32.u64 %0, t; }" : "=r"(a) : "l"(p));
    return a;
}
__device__ __forceinline__ void cp16(uint32_t dst, const void* src) {
    asm volatile("cp.async.cg.shared.global [%0], [%1], 16;" :: "r"(dst), "l"(src));
}
#define CP_COMMIT() asm volatile("cp.async.commit_group;" ::: "memory")
#define CP_WAIT(n)  asm volatile("cp.async.wait_group %0;" :: "n"(n) : "memory")

#define LDSM4(r, addr)                                                          \
    asm volatile("ldmatrix.sync.aligned.m8n8.x4.shared.b16 {%0,%1,%2,%3}, [%4];"\
        : "=r"((r)[0]), "=r"((r)[1]), "=r"((r)[2]), "=r"((r)[3]) : "r"(addr))

#define MMA(c, a, b)                                                            \
    asm volatile("mma.sync.aligned.m16n8k16.row.col.f32.f16.f16.f32 "           \
        "{%0,%1,%2,%3}, {%4,%5,%6,%7}, {%8,%9}, {%0,%1,%2,%3};"                 \
        : "+f"((c)[0]), "+f"((c)[1]), "+f"((c)[2]), "+f"((c)[3])                \
        : "r"((a)[0]), "r"((a)[1]), "r"((a)[2]), "r"((a)[3]),                   \
          "r"((b)[0]), "r"((b)[1]))

__device__ __forceinline__ uint32_t h2u(__half2 h) { return *(uint32_t*)&h; }

// ---------------------------------------------------------------------------
// K0: W [fin][fout] fp32 -> fp16 K-major [fout][fin]
// ---------------------------------------------------------------------------
__global__ void k0_wprep(const float* __restrict__ W) {
    int k = blockIdx.x, n = threadIdx.x;
    g_Whi[n * 256 + k] = __float2half_rn(W[k * 256 + n]);
}

// ---------------------------------------------------------------------------
// KS: S = input @ W, single-pass fp16 HMMA, 512 threads / 16 warps.
// Warp tile 32m x 64n (acc 64 regs). CTA = 128 rows x 256 cols. grid 2560.
// smem: [B resident 131072][F fp32 stage 32768][H fp16 2 x 16384] = 196608.
// ---------------------------------------------------------------------------
#define SMEM_KS 196608
#define SM_F 131072
#define SM_H 163840

__global__ __launch_bounds__(512, 1) void kS_gemm(const float* __restrict__ input) {
    extern __shared__ char smem[];
    const uint32_t sb = smem_u32(smem);
    const int tid = threadIdx.x, lane = tid & 31, wid = tid >> 5;
    const int wr = wid >> 2;           // 0..3  row group (x32)
    const int wc = wid & 3;            // 0..3  col group (x64)
    const size_t rowBase = (size_t)blockIdx.x * 128;

    // ---- resident B: [kcc 4][256 rows x 128B, swizzled] ----
    {
        const char* bB = (const char*)g_Whi;
#pragma unroll
        for (int it = 0; it < 16; ++it) {
            int u = it * 512 + tid;
            int kcc = u >> 11, r = (u >> 3) & 255, o = u & 7;
            size_t gb = (size_t)r * 512 + (size_t)kcc * 128 + o * 16;
            uint32_t so = (uint32_t)kcc * 32768 + r * 128 + ((o ^ (r & 7)) << 4);
            cp16(sb + so, bB + gb);
        }
    }

    // ---- A path: cp.async fp32 -> F, convert F -> H (swizzled fp16) ----
    auto loadF = [&](int kcc) {
#pragma unroll
        for (int it = 0; it < 4; ++it) {
            int u = it * 512 + tid;                 // 0..2047 16B units
            int row = u >> 4, o = u & 15;
            const char* src = (const char*)(input + (rowBase + row) * 256 +
                                            (size_t)kcc * 64 + o * 4);
            cp16(sb + SM_F + (uint32_t)u * 16, src);
        }
    };
    auto convertF = [&](int hbuf) {
        char* hb = smem + SM_H + hbuf * 16384;
#pragma unroll
        for (int it = 0; it < 4; ++it) {
            int u = it * 512 + tid;
            int row = u >> 4, o = u & 15;
            float4 v = *(const float4*)(smem + SM_F + (size_t)u * 16);
            uint2 w;
            w.x = h2u(__floats2half2_rn(v.x, v.y));
            w.y = h2u(__floats2half2_rn(v.z, v.w));
            *(uint2*)(hb + (uint32_t)row * 128 +
                      ((((uint32_t)o >> 1) ^ (uint32_t)(row & 7)) << 4) +
                      (uint32_t)(o & 1) * 8) = w;
        }
    };

    loadF(0);
    CP_COMMIT();          // group: B + F0
    CP_WAIT(0);
    __syncthreads();
    convertF(0);
    __syncthreads();
    loadF(1);
    CP_COMMIT();

    float acc[2][8][4];
#pragma unroll
    for (int mt = 0; mt < 2; ++mt)
#pragma unroll
        for (int nt = 0; nt < 8; ++nt)
#pragma unroll
            for (int q = 0; q < 4; ++q) acc[mt][nt][q] = 0.f;

    const int aRow0 = wr * 32 + (lane & 15);
    const int aKU = lane >> 4;
    const int aSw = lane & 7;
    const int bN0 = wc * 64 + (lane & 7) + ((lane >> 4) & 1) * 8;
    const int bKU = (lane >> 3) & 1;

#pragma unroll
    for (int kcc = 0; kcc < 4; ++kcc) {
        const uint32_t as = sb + SM_H + (uint32_t)(kcc & 1) * 16384;
        const uint32_t bs = sb + (uint32_t)kcc * 32768;
#pragma unroll
        for (int kk = 0; kk < 4; ++kk) {
            uint32_t ahi[2][4];
#pragma unroll
            for (int mt = 0; mt < 2; ++mt) {
                uint32_t off = (uint32_t)(aRow0 + mt * 16) * 128 +
                               (uint32_t)(((kk * 2 + aKU) ^ aSw) << 4);
                LDSM4(ahi[mt], as + off);
            }
#pragma unroll
            for (int half = 0; half < 2; ++half) {
                uint32_t bf[4][2];
#pragma unroll
                for (int p = 0; p < 2; ++p) {
                    uint32_t off = (uint32_t)(bN0 + half * 32 + p * 16) * 128 +
                                   (uint32_t)(((kk * 2 + bKU) ^ aSw) << 4);
                    uint32_t r[4];
                    LDSM4(r, bs + off);
                    bf[2 * p][0] = r[0]; bf[2 * p][1] = r[1];
                    bf[2 * p + 1][0] = r[2]; bf[2 * p + 1][1] = r[3];
                }
#pragma unroll
                for (int mt = 0; mt < 2; ++mt)
#pragma unroll
                    for (int q = 0; q < 4; ++q)
                        MMA(acc[mt][half * 4 + q], ahi[mt], bf[q]);
            }
        }
        if (kcc < 3) {
            CP_WAIT(0);                    // F(kcc+1) landed
            __syncthreads();               // all warps done with H(kcc^1)
            convertF((kcc + 1) & 1);
            __syncthreads();
            if (kcc < 2) {
                loadF(kcc + 2);
                CP_COMMIT();
            }
        }
    }

    // ---- epilogue: stage fp16 S (swizzled, B region dead) -> coalesced out --
    __syncthreads();
    char* yst = smem + 8192;
    float* st = (float*)smem;     // [16 warps][2 stats][64 cols]  (8 KB)
    {
        const int rl = wr * 32 + (lane >> 2);
        const int cq = (lane & 3) * 2;
#pragma unroll
        for (int mt = 0; mt < 2; ++mt)
#pragma unroll
            for (int h = 0; h < 2; ++h) {
                const int row = rl + mt * 16 + h * 8;
                const uint32_t sw = (uint32_t)(row & 7) << 4;
#pragma unroll
                for (int nt = 0; nt < 8; ++nt) {
                    const int col = wc * 64 + nt * 8 + cq;
                    __half2 hv = __floats2half2_rn(acc[mt][nt][2 * h],
                                                   acc[mt][nt][2 * h + 1]);
                    *(__half2*)(yst + ((uint32_t)row * 512 + (((uint32_t)col * 2) ^ sw))) = hv;
                }
            }
    }
    __syncthreads();
    {
        char* sg = (char*)g_S + rowBase * 512;
#pragma unroll
        for (int i = 0; i < 8; ++i) {
            int u = tid + 512 * i;
            int row = u >> 5, o = (u & 31) * 16;
            uint4 v = *(const uint4*)(yst + (uint32_t)row * 512 +
                                      ((uint32_t)o ^ ((uint32_t)(row & 7) << 4)));
            *(uint4*)(sg + (size_t)row * 512 + o) = v;
        }
    }
}

// ---------------------------------------------------------------------------
// KY: Y[b, s+r, f] = sum_c adj[b,s+r,s+c] * S[b,s+c,f]; fp16 Y out + stats.
// grid (4 blocks, 64 bgs of 128 batches), 256 threads (one per f).
// ---------------------------------------------------------------------------
__global__ __launch_bounds__(256, 1) void kY_apply(const float* __restrict__ adj) {
    __shared__ float sadj[128][100];
    const int i = blockIdx.x, s = i * 10;
    const int bg = blockIdx.y;
    const int f = threadIdx.x;

    for (int u = f; u < 12800; u += 256) {
        int bi = u / 100, rc = u % 100;
        int b = bg * 128 + bi;
        sadj[bi][rc] = adj[((size_t)b * 40 + s + rc / 10) * 40 + s + rc % 10];
    }
    __syncthreads();

    float st[10], st2[10];
#pragma unroll
    for (int r = 0; r < 10; ++r) { st[r] = 0.f; st2[r] = 0.f; }

    for (int bi = 0; bi < 128; ++bi) {
        const int b = bg * 128 + bi;
        const __half* sp = g_S + ((size_t)b * 40 + s) * 256 + f;
        float x[10];
#pragma unroll
        for (int c = 0; c < 10; ++c) x[c] = __half2float(sp[c * 256]);
        __half* yp = g_Yh + ((size_t)b * 40 + s) * 256 + f;
#pragma unroll
        for (int r = 0; r < 10; ++r) {
            float y = 0.f;
#pragma unroll
            for (int c = 0; c < 10; ++c) y = fmaf(sadj[bi][r * 10 + c], x[c], y);
            yp[r * 256] = __float2half_rn(y);
            st[r] += y;
            st2[r] = fmaf(y, y, st2[r]);
        }
    }
    float* gp = g_spY + (size_t)(i * 64 + bg) * 5120;
#pragma unroll
    for (int r = 0; r < 10; ++r) {
        gp[r * 256 + f] = st[r];
        gp[2560 + r * 256 + f] = st2[r];
    }
}

// ---------------------------------------------------------------------------
// K3b1: fold 8 bgs per group. grid (40, 8), 256 threads.
// ---------------------------------------------------------------------------
__global__ void k3b1_fold() {
    const int n = blockIdx.x, y = blockIdx.y, col = threadIdx.x;
    const int i = n / 10, r = n % 10;
    float s = 0.f, s2 = 0.f;
#pragma unroll
    for (int j = 0; j < 8; ++j) {
        const float* gp = g_spY + (size_t)(i * 64 + y * 8 + j) * 5120 + r * 256 + col;
        s += gp[0];
        s2 += gp[2560];
    }
    float* o = g_spY2 + (size_t)(n * 8 + y) * 512;
    o[col] = s;
    o[256 + col] = s2;
}

// K3b2: final fold -> scale/shift. grid 40, 256 threads.
__global__ void k3b2_scaleshift(const float* __restrict__ gamma,
                                const float* __restrict__ beta) {
    const int n = blockIdx.x, col = threadIdx.x;
    const int i = n / 10;
    float s = 0.f, s2 = 0.f;
#pragma unroll
    for (int y = 0; y < 8; ++y) {
        const float* gp = g_spY2 + (size_t)(n * 8 + y) * 512;
        s += gp[col];
        s2 += gp[256 + col];
    }
    const float inv = 1.f / (float)B_;
    float mean = s * inv;
    float var = fmaxf(s2 * inv - mean * mean, 0.f);
    int nf = n * 256 + col;
    float sc = gamma[i * NF + nf] * rsqrtf(var + 1e-5f);
    float bsum = beta[nf] + beta[NF + nf] + beta[2 * NF + nf] + beta[3 * NF + nf];
    g_scale[nf] = sc;
    g_shift[nf] = fmaf(-mean, sc, bsum);
}

// ---------------------------------------------------------------------------
// K4: out = Yh * scale + shift (fp16 read, fp32 write). 8 elems/thread.
// ---------------------------------------------------------------------------
__global__ void k4_normalize(float* __restrict__ out) {
    const size_t gid = (size_t)blockIdx.x * blockDim.x + threadIdx.x;
    uint4 raw = ((const uint4*)g_Yh)[gid];
    const int col8 = (int)(gid & 31);
    const int grow = (int)(gid >> 5);
    const int n = grow % 40;
    const float* scp = g_scale + n * 256 + col8 * 8;
    const float* shp = g_shift + n * 256 + col8 * 8;
    float4 sc0 = *(const float4*)scp, sc1 = *(const float4*)(scp + 4);
    float4 sh0 = *(const float4*)shp, sh1 = *(const float4*)(shp + 4);
    const __half2* hp = (const __half2*)&raw;
    float2 f0 = __half22float2(hp[0]);
    float2 f1 = __half22float2(hp[1]);
    float2 f2 = __half22float2(hp[2]);
    float2 f3 = __half22float2(hp[3]);
    float4 o0, o1;
    o0.x = fmaf(f0.x, sc0.x, sh0.x);
    o0.y = fmaf(f0.y, sc0.y, sh0.y);
    o0.z = fmaf(f1.x, sc0.z, sh0.z);
    o0.w = fmaf(f1.y, sc0.w, sh0.w);
    o1.x = fmaf(f2.x, sc1.x, sh1.x);
    o1.y = fmaf(f2.y, sc1.y, sh1.y);
    o1.z = fmaf(f3.x, sc1.z, sh1.z);
    o1.w = fmaf(f3.y, sc1.w, sh1.w);
    float* op = out + (size_t)grow * 256 + col8 * 8;
    *(float4*)op = o0;
    *(float4*)(op + 4) = o1;
}

// ---------------------------------------------------------------------------
extern "C" void kernel_launch(void* const* d_in, const int* in_sizes, int n_in,
                              void* d_out, int out_size) {
    const float* input = (const float*)d_in[0];
    const float* adj   = (const float*)d_in[1];
    const float* W     = (const float*)d_in[2];
    const float* gamma = (const float*)d_in[3];
    const float* beta  = (const float*)d_in[4];
    float* out = (float*)d_out;

    static bool inited = false;
    if (!inited) {
        cudaFuncSetAttribute(kS_gemm, cudaFuncAttributeMaxDynamicSharedMemorySize, SMEM_KS);
        inited = true;
    }

    k0_wprep<<<256, 256>>>(W);
    kS_gemm<<<2560, 512, SMEM_KS>>>(input);
    kY_apply<<<dim3(4, 64), 256>>>(adj);
    k3b1_fold<<<dim3(40, 8), 256>>>();
    k3b2_scaleshift<<<40, 256>>>(gamma, beta);
    k4_normalize<<<(TOT / 8) / 256, 256>>>(out);
}